// round 10
// baseline (speedup 1.0000x reference)
#include <cuda_runtime.h>
#include <cuda_fp16.h>
#include <cstdint>
#include <cstddef>

#define Bb 16
#define Tt 128
#define Dd 256
#define HCOLS 128
#define NTHREADS 512

// smem layout (bytes)
#define OFF_WA   0
#define SZ_WA    (16 * NTHREADS * 16)      // 131072: fp16 w+alpha interleaved uint4 rows
#define OFF_YB   (OFF_WA + SZ_WA)
#define YSLOT_H  320                        // halves per slot (4 chunks of 72 + pad)
#define SZ_YB    (2 * 4 * YSLOT_H * 2)      // 5120
#define OFF_Y0H  (OFF_YB + SZ_YB)
#define SZ_Y0H   (2 * 4 * HCOLS * 2)        // 2048
#define OFF_XT   (OFF_Y0H + SZ_Y0H)
#define SZ_XT    (2 * Tt * 4)               // 1024
#define OFF_RED  (OFF_XT + SZ_XT)
#define SZ_RED   (32 * 4)                   // redbuf[2 parities][16]
#define OFF_MB   (OFF_RED + SZ_RED)
#define SZ_MB    (8 * 8)
#define SMEM_TOTAL (OFF_MB + SZ_MB)

__device__ __forceinline__ uint32_t my_cluster_rank() {
    uint32_t r; asm("mov.u32 %0, %%cluster_ctarank;" : "=r"(r)); return r;
}
__device__ __forceinline__ void cluster_sync_() {
    asm volatile("barrier.cluster.arrive.aligned;" ::: "memory");
    asm volatile("barrier.cluster.wait.aligned;" ::: "memory");
}
__device__ __forceinline__ uint32_t mapa_u32(uint32_t laddr, uint32_t rank) {
    uint32_t r;
    asm("mapa.shared::cluster.u32 %0, %1, %2;" : "=r"(r) : "r"(laddr), "r"(rank));
    return r;
}
__device__ __forceinline__ void st_remote_u16(uint32_t addr, __half v) {
    asm volatile("st.shared::cluster.u16 [%0], %1;"
                 :: "r"(addr), "h"(__half_as_ushort(v)) : "memory");
}
__device__ __forceinline__ void mb_init(uint32_t addr, uint32_t count) {
    asm volatile("mbarrier.init.shared.b64 [%0], %1;" :: "r"(addr), "r"(count) : "memory");
}
__device__ __forceinline__ void mb_arrive_remote(uint32_t raddr) {
    asm volatile("mbarrier.arrive.release.cluster.shared::cluster.b64 _, [%0];"
                 :: "r"(raddr) : "memory");
}
__device__ __forceinline__ void mb_arrive_local(uint32_t addr) {
    asm volatile("mbarrier.arrive.release.cta.shared::cta.b64 _, [%0];"
                 :: "r"(addr) : "memory");
}
__device__ __forceinline__ void mb_wait(uint32_t addr, uint32_t parity) {
    uint32_t done;
    asm volatile(
        "{\n\t.reg .pred p;\n\t"
        "mbarrier.try_wait.parity.acquire.cluster.shared::cta.b64 p, [%1], %2;\n\t"
        "selp.b32 %0, 1, 0, p;\n\t}"
        : "=r"(done) : "r"(addr), "r"(parity) : "memory");
    while (!done) {
        asm volatile(
            "{\n\t.reg .pred p;\n\t"
            "mbarrier.try_wait.parity.acquire.cluster.shared::cta.b64 p, [%1], %2, 0x989680;\n\t"
            "selp.b32 %0, 1, 0, p;\n\t}"
            : "=r"(done) : "r"(addr), "r"(parity) : "memory");
    }
}
__device__ __forceinline__ float tanh_ap(float x) {
    float y; asm("tanh.approx.f32 %0, %1;" : "=f"(y) : "f"(x)); return y;
}
__device__ __forceinline__ float grp4_sum(float v) {
    v += __shfl_xor_sync(0xffffffffu, v, 1);
    v += __shfl_xor_sync(0xffffffffu, v, 2);
    return v;
}

__global__ void __launch_bounds__(NTHREADS, 1) __cluster_dims__(4, 1, 1)
plastic_kernel(const int* __restrict__ x, const float* __restrict__ emb,
               const float* __restrict__ ws, const float* __restrict__ alphas,
               const float* __restrict__ etas, float* __restrict__ out)
{
    extern __shared__ __align__(16) char smem_raw[];
    uint4*  wa     = reinterpret_cast<uint4*>(smem_raw + OFF_WA);    // [16][512]
    __half* ybuf   = reinterpret_cast<__half*>(smem_raw + OFF_YB);   // [2][4][YSLOT_H]
    __half* y0h    = reinterpret_cast<__half*>(smem_raw + OFF_Y0H);  // [2][4][128]
    int*    xtok   = reinterpret_cast<int*>(smem_raw + OFF_XT);      // [2][128]
    float*  redbuf = reinterpret_cast<float*>(smem_raw + OFF_RED);   // [2][16]
    const uint32_t sbase = (uint32_t)__cvta_generic_to_shared(smem_raw);

    const int tid     = threadIdx.x;
    const int cluster = blockIdx.x >> 2;
    const int rank    = (int)my_cluster_rank();
    const int layer   = rank >> 1;
    const int half_   = rank & 1;
    const int col_off = half_ * HCOLS;
    const int partner = rank ^ 1;
    const int col     = tid >> 2;            // 0..127
    const int colg    = col_off + col;
    const int dgrp    = tid & 3;             // 0..3 (d-range dgrp*64..+64)
    const int wid     = tid >> 5, lane = tid & 31;
    const int pcol    = (colg >> 6) * 72 + (colg & 63);
    const int ptid    = (tid >> 6) * 72 + (tid & 63);

#define MB_ADDR(b, s)  (sbase + OFF_MB + (uint32_t)(((b) * 4 + (s)) * 8))
#define YB_SLOT(b, s)  (ybuf + ((b) * 4 + (s)) * YSLOT_H)
#define Y0H_SLOT(b, s) (y0h + ((b) * 4 + (s)) * HCOLS)

    // ---- init shared ----
    for (int i = tid; i < 2 * 4 * YSLOT_H; i += NTHREADS) ybuf[i] = __ushort_as_half(0);
    for (int i = tid; i < 2 * 4 * HCOLS; i += NTHREADS) y0h[i] = __ushort_as_half(0);
    for (int i = tid; i < 2 * Tt; i += NTHREADS)
        xtok[i] = x[(cluster * 2 + (i >> 7)) * Tt + (i & 127)];
    if (tid == 0)
        for (int k = 0; k < 8; k++) mb_init(sbase + OFF_MB + 8u * k, 48);
    __syncthreads();

    const float eta = etas[layer];
    const __half2 om2 = __float2half2_rn(1.0f - eta);

    __half2 h2a[32], h2b[32];
#pragma unroll
    for (int i = 0; i < 32; i++) { h2a[i] = __float2half2_rn(0.f); h2b[i] = h2a[i]; }

    // ---- stage w + alpha (fp16) into interleaved per-thread chunks ----
    {
        const float* wsrc = ws     + (size_t)layer * Dd * Dd;
        const float* asrc = alphas + (size_t)layer * Dd * Dd;
        for (int idx = tid; idx < Dd * HCOLS; idx += NTHREADS) {
            int d = idx >> 7, c = idx & 127;
            int o = c * 4 + (d >> 6);
            int j = (d & 63) >> 3;
            int k = d & 7;
            float wv = wsrc[(size_t)d * Dd + col_off + c];
            float av = asrc[(size_t)d * Dd + col_off + c];
            reinterpret_cast<__half*>(&wa[(2 * j) * NTHREADS + o])[k]     = __float2half(wv);
            reinterpret_cast<__half*>(&wa[(2 * j + 1) * NTHREADS + o])[k] = __float2half(av);
        }
    }
    __syncthreads();

    const uint32_t del_partner = mapa_u32(sbase, (uint32_t)partner) - sbase;
    const uint32_t del_inter   = (layer == 0)
        ? (mapa_u32(sbase, (uint32_t)(rank + 2)) - sbase)
        : (mapa_u32(sbase, (uint32_t)(rank - 2)) - sbase);

    cluster_sync_();   // barriers armed everywhere before any arrive

    // ---- startup arrives: every warp's lane0 ----
    if (lane == 0) {
#pragma unroll
        for (int B = 0; B < 2; B++) {
            mb_arrive_remote(MB_ADDR(B, 0) + del_partner);
            mb_arrive_local(MB_ADDR(B, 0));
            if (layer == 1) {
#pragma unroll
                for (int s = 0; s < 4; s++)
                    mb_arrive_remote(MB_ADDR(B, s) + del_inter);
            }
        }
    }

    float* const outB0 = out + (size_t)(cluster * 2 + 0) * Tt * Dd;
    float* const outB1 = out + (size_t)(cluster * 2 + 1) * Tt * Dd;
    const uint4* wthr = wa + tid;

    float embreg0 = 0.f, embreg1 = 0.f;
    if (layer == 0) {
        embreg0 = __ldg(&emb[(size_t)xtok[0] * Dd + colg]);
        embreg1 = __ldg(&emb[(size_t)xtok[Tt] * Dd + colg]);
    }

    __half2 yc[32];   // yin cache, reused per batch

    for (int t = 0; t < Tt; ++t) {
        const int sc = t & 3, sp = (t + 3) & 3, n3 = (t + 1) & 3;
        const uint32_t par = (uint32_t)((t >> 2) & 1);

        // hoisted waits: both batches (producer slack overlaps)
        mb_wait(MB_ADDR(0, sc), par);
        mb_wait(MB_ADDR(1, sc), par);

#define STEP_BATCH(B, H2, EMBREG)                                                  \
        {                                                                          \
            const uint4* yp = reinterpret_cast<const uint4*>(                      \
                YB_SLOT(B, sp) + dgrp * 72);                                       \
            __half2 acc0 = __float2half2_rn(0.f), acc1 = acc0;                     \
            __half2 acc2 = acc0, acc3 = acc0;                                      \
            _Pragma("unroll")                                                      \
            for (int j = 0; j < 8; j++) {                                          \
                uint4 wv = wthr[(2 * j) * NTHREADS];                               \
                uint4 av = wthr[(2 * j + 1) * NTHREADS];                           \
                uint4 yv = yp[j];                                                  \
                __half2 y0 = *reinterpret_cast<__half2*>(&yv.x);                   \
                __half2 y1 = *reinterpret_cast<__half2*>(&yv.y);                   \
                __half2 y2 = *reinterpret_cast<__half2*>(&yv.z);                   \
                __half2 y3 = *reinterpret_cast<__half2*>(&yv.w);                   \
                yc[4 * j] = y0; yc[4 * j + 1] = y1;                                \
                yc[4 * j + 2] = y2; yc[4 * j + 3] = y3;                            \
                acc0 = __hfma2(y0, __hfma2(*reinterpret_cast<__half2*>(&av.x),     \
                                  H2[4 * j],     *reinterpret_cast<__half2*>(&wv.x)), acc0); \
                acc1 = __hfma2(y1, __hfma2(*reinterpret_cast<__half2*>(&av.y),     \
                                  H2[4 * j + 1], *reinterpret_cast<__half2*>(&wv.y)), acc1); \
                acc2 = __hfma2(y2, __hfma2(*reinterpret_cast<__half2*>(&av.z),     \
                                  H2[4 * j + 2], *reinterpret_cast<__half2*>(&wv.z)), acc2); \
                acc3 = __hfma2(y3, __hfma2(*reinterpret_cast<__half2*>(&av.w),     \
                                  H2[4 * j + 3], *reinterpret_cast<__half2*>(&wv.w)), acc3); \
            }                                                                      \
            float2 f0 = __half22float2(__hadd2(acc0, acc1));                       \
            float2 f1 = __half22float2(__hadd2(acc2, acc3));                       \
            float acc = grp4_sum((f0.x + f0.y) + (f1.x + f1.y));                   \
            float inp = (layer == 0) ? EMBREG                                      \
                                     : __half2float(Y0H_SLOT(B, sc)[col]);         \
            float y = tanh_ap(acc + inp);                                          \
            __half yh = __float2half(y);                                           \
            __half* yb = YB_SLOT(B, sc);                                           \
            if (dgrp == 1) yb[pcol] = yh;                                          \
            if (dgrp == 0)                                                         \
                st_remote_u16((uint32_t)__cvta_generic_to_shared(yb + pcol)        \
                              + del_partner, yh);                                  \
            if (dgrp == 2 && layer == 0)                                           \
                st_remote_u16((uint32_t)__cvta_generic_to_shared(                  \
                                  Y0H_SLOT(B, sc) + col) + del_inter, yh);         \
            __syncwarp();                                                          \
            if (lane == 0) {                                                       \
                mb_arrive_remote(MB_ADDR(B, n3) + del_partner);                    \
                mb_arrive_local(MB_ADDR(B, n3));                                   \
                mb_arrive_remote(MB_ADDR(B, sc) + del_inter);                      \
            }                                                                      \
            {                                                                      \
                __half2 ey2 = __float2half2_rn(eta * y);                           \
                _Pragma("unroll")                                                  \
                for (int i = 0; i < 32; i++)                                       \
                    H2[i] = __hfma2(H2[i], om2, __hmul2(yc[i], ey2));              \
            }                                                                      \
            if (layer == 0 && t + 1 < Tt)                                          \
                EMBREG = __ldg(&emb[(size_t)xtok[B * Tt + t + 1] * Dd + colg]);    \
        }

        STEP_BATCH(0, h2a, embreg0)
        STEP_BATCH(1, h2b, embreg1)

        if (layer == 1 && t >= 1) {
            float* rb = redbuf + (t & 1) * 16;
            float ex0 = 0.f, ex1 = 0.f;
            if (tid < Dd) {
                float v0 = __half2float(YB_SLOT(0, sp)[ptid]);
                float v1 = __half2float(YB_SLOT(1, sp)[ptid]);
                ex0 = __expf(__fdividef(1.0f, 1.0f + __expf(-v0)));
                ex1 = __expf(__fdividef(1.0f, 1.0f + __expf(-v1)));
            }
            float w0 = ex0, w1 = ex1;
#pragma unroll
            for (int o = 16; o >= 1; o >>= 1) {
                w0 += __shfl_xor_sync(0xffffffffu, w0, o);
                w1 += __shfl_xor_sync(0xffffffffu, w1, o);
            }
            if (wid < 8 && lane == 0) { rb[wid] = w0; rb[8 + wid] = w1; }
            __syncthreads();
            float t0 = 0.f, t1 = 0.f;
#pragma unroll
            for (int k = 0; k < 8; k++) { t0 += rb[k]; t1 += rb[8 + k]; }
            if (tid >= col_off && tid < col_off + HCOLS) {
                outB0[(size_t)(t - 1) * Dd + tid] = __fdividef(ex0, t0);
                outB1[(size_t)(t - 1) * Dd + tid] = __fdividef(ex1, t1);
            }
        }
    }

    // ---- epilogue ----
    if (layer == 0) {
        if (lane == 0) {   // bonus inter arrives so L1's final slot-0 phase completes
            mb_arrive_remote(MB_ADDR(0, 0) + del_inter);
            mb_arrive_remote(MB_ADDR(1, 0) + del_inter);
        }
    } else {
        mb_wait(MB_ADDR(0, 0), 0u);
        mb_wait(MB_ADDR(1, 0), 0u);
        const int sp = 3;
        float* rb = redbuf;   // parity 0 set; safe: last loop softmax used parity 1
        float ex0 = 0.f, ex1 = 0.f;
        if (tid < Dd) {
            float v0 = __half2float(YB_SLOT(0, sp)[ptid]);
            float v1 = __half2float(YB_SLOT(1, sp)[ptid]);
            ex0 = __expf(__fdividef(1.0f, 1.0f + __expf(-v0)));
            ex1 = __expf(__fdividef(1.0f, 1.0f + __expf(-v1)));
        }
        float w0 = ex0, w1 = ex1;
#pragma unroll
        for (int o = 16; o >= 1; o >>= 1) {
            w0 += __shfl_xor_sync(0xffffffffu, w0, o);
            w1 += __shfl_xor_sync(0xffffffffu, w1, o);
        }
        if (wid < 8 && lane == 0) { rb[wid] = w0; rb[8 + wid] = w1; }
        __syncthreads();
        float t0 = 0.f, t1 = 0.f;
#pragma unroll
        for (int k = 0; k < 8; k++) { t0 += rb[k]; t1 += rb[8 + k]; }
        if (tid >= col_off && tid < col_off + HCOLS) {
            outB0[(size_t)(Tt - 1) * Dd + tid] = __fdividef(ex0, t0);
            outB1[(size_t)(Tt - 1) * Dd + tid] = __fdividef(ex1, t1);
        }
    }

    cluster_sync_();
}

extern "C" void kernel_launch(void* const* d_in, const int* in_sizes, int n_in,
                              void* d_out, int out_size) {
    const int*   x      = (const int*)d_in[0];
    const float* emb    = (const float*)d_in[1];
    const float* ws     = (const float*)d_in[2];
    const float* alphas = (const float*)d_in[3];
    const float* etas   = (const float*)d_in[4];
    cudaFuncSetAttribute(plastic_kernel,
                         cudaFuncAttributeMaxDynamicSharedMemorySize, SMEM_TOTAL);
    plastic_kernel<<<(Bb / 2) * 4, NTHREADS, SMEM_TOTAL>>>(
        x, emb, ws, alphas, etas, (float*)d_out);
}

// round 11
// speedup vs baseline: 1.3048x; 1.3048x over previous
#include <cuda_runtime.h>
#include <cuda_fp16.h>
#include <cstdint>
#include <cstddef>

#define Bb 16
#define Tt 128
#define Dd 256
#define HCOLS 128
#define NTHREADS 1024

// smem layout (bytes)
#define OFF_WA   0
#define SZ_WA    (8 * NTHREADS * 16)       // 131072: fp16 w+alpha interleaved uint4 rows
#define OFF_YB   (OFF_WA + SZ_WA)
#define YSLOT_H  320                        // halves per slot: 8 chunks of (32 data + 8 pad)
#define SZ_YB    (2 * 4 * YSLOT_H * 2)      // 5120
#define OFF_Y0H  (OFF_YB + SZ_YB)
#define SZ_Y0H   (2 * 4 * HCOLS * 2)        // 2048
#define OFF_XT   (OFF_Y0H + SZ_Y0H)
#define SZ_XT    (2 * Tt * 4)               // 1024
#define OFF_RED  (OFF_XT + SZ_XT)
#define SZ_RED   (32 * 4)                   // redbuf[2 parities][16]
#define OFF_MB   (OFF_RED + SZ_RED)
#define SZ_MB    (4 * 8)                    // 4 slot barriers
#define SMEM_TOTAL (OFF_MB + SZ_MB)

__device__ __forceinline__ uint32_t my_cluster_rank() {
    uint32_t r; asm("mov.u32 %0, %%cluster_ctarank;" : "=r"(r)); return r;
}
__device__ __forceinline__ void cluster_sync_() {
    asm volatile("barrier.cluster.arrive.aligned;" ::: "memory");
    asm volatile("barrier.cluster.wait.aligned;" ::: "memory");
}
__device__ __forceinline__ uint32_t mapa_u32(uint32_t laddr, uint32_t rank) {
    uint32_t r;
    asm("mapa.shared::cluster.u32 %0, %1, %2;" : "=r"(r) : "r"(laddr), "r"(rank));
    return r;
}
__device__ __forceinline__ void st_remote_u16(uint32_t addr, __half v) {
    asm volatile("st.shared::cluster.u16 [%0], %1;"
                 :: "r"(addr), "h"(__half_as_ushort(v)) : "memory");
}
__device__ __forceinline__ void mb_init(uint32_t addr, uint32_t count) {
    asm volatile("mbarrier.init.shared.b64 [%0], %1;" :: "r"(addr), "r"(count) : "memory");
}
__device__ __forceinline__ void mb_arrive_remote(uint32_t raddr) {
    asm volatile("mbarrier.arrive.release.cluster.shared::cluster.b64 _, [%0];"
                 :: "r"(raddr) : "memory");
}
__device__ __forceinline__ void mb_wait(uint32_t addr, uint32_t parity) {
    uint32_t done;
    asm volatile(
        "{\n\t.reg .pred p;\n\t"
        "mbarrier.try_wait.parity.acquire.cluster.shared::cta.b64 p, [%1], %2;\n\t"
        "selp.b32 %0, 1, 0, p;\n\t}"
        : "=r"(done) : "r"(addr), "r"(parity) : "memory");
    while (!done) {
        asm volatile(
            "{\n\t.reg .pred p;\n\t"
            "mbarrier.try_wait.parity.acquire.cluster.shared::cta.b64 p, [%1], %2, 0x989680;\n\t"
            "selp.b32 %0, 1, 0, p;\n\t}"
            : "=r"(done) : "r"(addr), "r"(parity) : "memory");
    }
}
__device__ __forceinline__ float tanh_ap(float x) {
    float y; asm("tanh.approx.f32 %0, %1;" : "=f"(y) : "f"(x)); return y;
}
__device__ __forceinline__ float grp8_sum(float v) {
    v += __shfl_xor_sync(0xffffffffu, v, 1);
    v += __shfl_xor_sync(0xffffffffu, v, 2);
    v += __shfl_xor_sync(0xffffffffu, v, 4);
    return v;
}

__global__ void __launch_bounds__(NTHREADS, 1) __cluster_dims__(4, 1, 1)
plastic_kernel(const int* __restrict__ x, const float* __restrict__ emb,
               const float* __restrict__ ws, const float* __restrict__ alphas,
               const float* __restrict__ etas, float* __restrict__ out)
{
    extern __shared__ __align__(16) char smem_raw[];
    uint4*  wa     = reinterpret_cast<uint4*>(smem_raw + OFF_WA);    // [8][1024]
    __half* ybuf   = reinterpret_cast<__half*>(smem_raw + OFF_YB);   // [2][4][320]
    __half* y0h    = reinterpret_cast<__half*>(smem_raw + OFF_Y0H);  // [2][4][128]
    int*    xtok   = reinterpret_cast<int*>(smem_raw + OFF_XT);      // [2][128]
    float*  redbuf = reinterpret_cast<float*>(smem_raw + OFF_RED);   // [2][16]
    const uint32_t sbase = (uint32_t)__cvta_generic_to_shared(smem_raw);

    const int tid     = threadIdx.x;
    const int cluster = blockIdx.x >> 2;
    const int rank    = (int)my_cluster_rank();
    const int layer   = rank >> 1;
    const int half_   = rank & 1;
    const int col_off = half_ * HCOLS;
    const int partner = rank ^ 1;
    const int col     = tid >> 3;            // 0..127
    const int colg    = col_off + col;
    const int dgrp    = tid & 7;             // 0..7, d-range [dgrp*32, dgrp*32+32)
    const int wid     = tid >> 5, lane = tid & 31;
    // y slot layout: 8 chunks of 40 halves (32 data + 8 pad) -> conflict-free dgrp reads
    const int pcol    = (colg >> 5) * 40 + (colg & 31);   // write pos for y[colg]
    const int ptid    = (tid >> 5) * 40 + (tid & 31);     // softmax read pos (tid<256)

#define MB_ADDR(s)     (sbase + OFF_MB + (uint32_t)((s) * 8))
#define YB_SLOT(b, s)  (ybuf + ((b) * 4 + (s)) * YSLOT_H)
#define Y0H_SLOT(b, s) (y0h + ((b) * 4 + (s)) * HCOLS)

    // ---- init shared ----
    for (int i = tid; i < 2 * 4 * YSLOT_H; i += NTHREADS) ybuf[i] = __ushort_as_half(0);
    for (int i = tid; i < 2 * 4 * HCOLS; i += NTHREADS) y0h[i] = __ushort_as_half(0);
    for (int i = tid; i < 2 * Tt; i += NTHREADS)
        xtok[i] = x[(cluster * 2 + (i >> 7)) * Tt + (i & 127)];
    if (tid == 0)
        for (int k = 0; k < 4; k++) mb_init(MB_ADDR(k), 2);
    __syncthreads();

    const float eta = etas[layer];
    const __half2 om2 = __float2half2_rn(1.0f - eta);

    __half2 h2a[16], h2b[16];
#pragma unroll
    for (int i = 0; i < 16; i++) { h2a[i] = __float2half2_rn(0.f); h2b[i] = h2a[i]; }

    // ---- stage w + alpha (fp16): thread o = c*8 + (d>>5) owns (32 d, 1 col) ----
    // row 2j = w uint4-chunk j (8 halves), row 2j+1 = alpha chunk j, j = 0..3
    {
        const float* wsrc = ws     + (size_t)layer * Dd * Dd;
        const float* asrc = alphas + (size_t)layer * Dd * Dd;
        for (int idx = tid; idx < Dd * HCOLS; idx += NTHREADS) {
            int d = idx >> 7, c = idx & 127;
            int o = c * 8 + (d >> 5);
            int j = (d & 31) >> 3;
            int k = d & 7;
            reinterpret_cast<__half*>(&wa[(2 * j) * NTHREADS + o])[k] =
                __float2half(wsrc[(size_t)d * Dd + col_off + c]);
            reinterpret_cast<__half*>(&wa[(2 * j + 1) * NTHREADS + o])[k] =
                __float2half(asrc[(size_t)d * Dd + col_off + c]);
        }
    }
    __syncthreads();

    const uint32_t del_partner = mapa_u32(sbase, (uint32_t)partner) - sbase;
    const uint32_t del_inter   = (layer == 0)
        ? (mapa_u32(sbase, (uint32_t)(rank + 2)) - sbase)
        : (mapa_u32(sbase, (uint32_t)(rank - 2)) - sbase);

    cluster_sync_();   // barriers armed + buffers zeroed everywhere

    // ---- startup arrives (count=2 per slot-phase) ----
    if (tid == 0)
        mb_arrive_remote(MB_ADDR(0) + del_partner);
    if (tid == 32 && layer == 1) {   // credits to my L0 for slots 0..3
#pragma unroll
        for (int s = 0; s < 4; s++)
            mb_arrive_remote(MB_ADDR(s) + del_inter);
    }

    float* const outB0 = out + (size_t)(cluster * 2 + 0) * Tt * Dd;
    float* const outB1 = out + (size_t)(cluster * 2 + 1) * Tt * Dd;
    const uint4* wthr = wa + tid;

    float embreg0 = 0.f, embreg1 = 0.f;
    if (layer == 0) {
        embreg0 = __ldg(&emb[(size_t)xtok[0] * Dd + colg]);
        embreg1 = __ldg(&emb[(size_t)xtok[Tt] * Dd + colg]);
    }

    for (int t = 0; t < Tt; ++t) {
        const int sc = t & 3, sp = (t + 3) & 3, n3 = (t + 1) & 3;
        const uint32_t par = (uint32_t)((t >> 2) & 1);

        mb_wait(MB_ADDR(sc), par);   // one wait: partner(t-1) + inter(y0 data / credit)

        // ---- fused dual-batch dot: w/alpha loaded once ----
        const uint4* yp0 = reinterpret_cast<const uint4*>(YB_SLOT(0, sp)) + dgrp * 5;
        const uint4* yp1 = reinterpret_cast<const uint4*>(YB_SLOT(1, sp)) + dgrp * 5;
        __half2 accA0 = __float2half2_rn(0.f), accA1 = accA0;
        __half2 accB0 = accA0, accB1 = accA0;
#pragma unroll
        for (int j = 0; j < 4; j++) {
            uint4 wv = wthr[(2 * j) * NTHREADS];
            uint4 av = wthr[(2 * j + 1) * NTHREADS];
            uint4 y0v = yp0[j];
            uint4 y1v = yp1[j];
#define LANE(F)  F(x, 4 * j + 0, accA0, accB0)  F(y, 4 * j + 1, accA1, accB1) \
                 F(z, 4 * j + 2, accA0, accB0)  F(w, 4 * j + 3, accA1, accB1)
#define DOT2(c, hi, aA, aB)                                                        \
            {                                                                      \
                __half2 wl = *reinterpret_cast<__half2*>(&wv.c);                   \
                __half2 al = *reinterpret_cast<__half2*>(&av.c);                   \
                aA = __hfma2(*reinterpret_cast<__half2*>(&y0v.c),                  \
                             __hfma2(al, h2a[hi], wl), aA);                        \
                aB = __hfma2(*reinterpret_cast<__half2*>(&y1v.c),                  \
                             __hfma2(al, h2b[hi], wl), aB);                        \
            }
            LANE(DOT2)
#undef DOT2
#undef LANE
        }
        float2 fA = __half22float2(__hadd2(accA0, accA1));
        float2 fB = __half22float2(__hadd2(accB0, accB1));
        float acc0 = grp8_sum(fA.x + fA.y);
        float acc1 = grp8_sum(fB.x + fB.y);

        float inp0 = (layer == 0) ? embreg0 : __half2float(Y0H_SLOT(0, sc)[col]);
        float inp1 = (layer == 0) ? embreg1 : __half2float(Y0H_SLOT(1, sc)[col]);
        float y0 = tanh_ap(acc0 + inp0);
        float y1 = tanh_ap(acc1 + inp1);
        __half yh0 = __float2half(y0), yh1 = __float2half(y1);

        // ---- stores: dgrp roles ----
        __half* yb0 = YB_SLOT(0, sc);
        __half* yb1 = YB_SLOT(1, sc);
        if (dgrp == 1) { yb0[pcol] = yh0; yb1[pcol] = yh1; }
        if (dgrp == 0) {
            st_remote_u16((uint32_t)__cvta_generic_to_shared(yb0 + pcol) + del_partner, yh0);
            st_remote_u16((uint32_t)__cvta_generic_to_shared(yb1 + pcol) + del_partner, yh1);
        }
        if (dgrp == 2 && layer == 0) {
            st_remote_u16((uint32_t)__cvta_generic_to_shared(Y0H_SLOT(0, sc) + col)
                          + del_inter, yh0);
            st_remote_u16((uint32_t)__cvta_generic_to_shared(Y0H_SLOT(1, sc) + col)
                          + del_inter, yh1);
        }
        __syncthreads();   // all stores issued before the 2 arrives

        if (tid == 0)  mb_arrive_remote(MB_ADDR(n3) + del_partner);
        if (tid == 32) mb_arrive_remote(MB_ADDR(sc) + del_inter);

        // ---- deferred: hebb (re-reads old y), emb prefetch, softmax ----
        {
            __half2 ey0 = __float2half2_rn(eta * y0);
            __half2 ey1 = __float2half2_rn(eta * y1);
#pragma unroll
            for (int j = 0; j < 4; j++) {
                uint4 y0v = yp0[j];
                uint4 y1v = yp1[j];
#define HEB(c, hi)                                                                 \
                h2a[hi] = __hfma2(h2a[hi], om2,                                    \
                    __hmul2(*reinterpret_cast<__half2*>(&y0v.c), ey0));            \
                h2b[hi] = __hfma2(h2b[hi], om2,                                    \
                    __hmul2(*reinterpret_cast<__half2*>(&y1v.c), ey1));
                HEB(x, 4 * j + 0) HEB(y, 4 * j + 1) HEB(z, 4 * j + 2) HEB(w, 4 * j + 3)
#undef HEB
            }
        }
        if (layer == 0 && t + 1 < Tt) {
            embreg0 = __ldg(&emb[(size_t)xtok[t + 1] * Dd + colg]);
            embreg1 = __ldg(&emb[(size_t)xtok[Tt + t + 1] * Dd + colg]);
        }

        if (layer == 1 && t >= 1) {
            float* rb = redbuf + (t & 1) * 16;
            float ex0 = 0.f, ex1 = 0.f;
            if (tid < Dd) {
                float v0 = __half2float(YB_SLOT(0, sp)[ptid]);
                float v1 = __half2float(YB_SLOT(1, sp)[ptid]);
                ex0 = __expf(__fdividef(1.0f, 1.0f + __expf(-v0)));
                ex1 = __expf(__fdividef(1.0f, 1.0f + __expf(-v1)));
            }
            float w0 = ex0, w1 = ex1;
#pragma unroll
            for (int o = 16; o >= 1; o >>= 1) {
                w0 += __shfl_xor_sync(0xffffffffu, w0, o);
                w1 += __shfl_xor_sync(0xffffffffu, w1, o);
            }
            if (wid < 8 && lane == 0) { rb[wid] = w0; rb[8 + wid] = w1; }
            __syncthreads();
            float t0 = 0.f, t1 = 0.f;
#pragma unroll
            for (int k = 0; k < 8; k++) { t0 += rb[k]; t1 += rb[8 + k]; }
            if (tid >= col_off && tid < col_off + HCOLS) {
                outB0[(size_t)(t - 1) * Dd + tid] = __fdividef(ex0, t0);
                outB1[(size_t)(t - 1) * Dd + tid] = __fdividef(ex1, t1);
            }
        }
    }

    // ---- epilogue ----
    if (layer == 0) {
        if (tid == 32)   // bonus inter so L1's final slot-0 phase completes
            mb_arrive_remote(MB_ADDR(0) + del_inter);
    } else {
        mb_wait(MB_ADDR(0), 0u);
        const int sp = 3;   // slot of y1(127)
        float* rb = redbuf;  // parity-0 half; last loop softmax used parity 1
        float ex0 = 0.f, ex1 = 0.f;
        if (tid < Dd) {
            float v0 = __half2float(YB_SLOT(0, sp)[ptid]);
            float v1 = __half2float(YB_SLOT(1, sp)[ptid]);
            ex0 = __expf(__fdividef(1.0f, 1.0f + __expf(-v0)));
            ex1 = __expf(__fdividef(1.0f, 1.0f + __expf(-v1)));
        }
        float w0 = ex0, w1 = ex1;
#pragma unroll
        for (int o = 16; o >= 1; o >>= 1) {
            w0 += __shfl_xor_sync(0xffffffffu, w0, o);
            w1 += __shfl_xor_sync(0xffffffffu, w1, o);
        }
        if (wid < 8 && lane == 0) { rb[wid] = w0; rb[8 + wid] = w1; }
        __syncthreads();
        float t0 = 0.f, t1 = 0.f;
#pragma unroll
        for (int k = 0; k < 8; k++) { t0 += rb[k]; t1 += rb[8 + k]; }
        if (tid >= col_off && tid < col_off + HCOLS) {
            outB0[(size_t)(Tt - 1) * Dd + tid] = __fdividef(ex0, t0);
            outB1[(size_t)(Tt - 1) * Dd + tid] = __fdividef(ex1, t1);
        }
    }

    cluster_sync_();
}

extern "C" void kernel_launch(void* const* d_in, const int* in_sizes, int n_in,
                              void* d_out, int out_size) {
    const int*   x      = (const int*)d_in[0];
    const float* emb    = (const float*)d_in[1];
    const float* ws     = (const float*)d_in[2];
    const float* alphas = (const float*)d_in[3];
    const float* etas   = (const float*)d_in[4];
    cudaFuncSetAttribute(plastic_kernel,
                         cudaFuncAttributeMaxDynamicSharedMemorySize, SMEM_TOTAL);
    plastic_kernel<<<(Bb / 2) * 4, NTHREADS, SMEM_TOTAL>>>(
        x, emb, ws, alphas, etas, (float*)d_out);
}

// round 12
// speedup vs baseline: 1.3470x; 1.0323x over previous
#include <cuda_runtime.h>
#include <cuda_fp16.h>
#include <cstdint>
#include <cstddef>

#define Bb 16
#define Tt 128
#define Dd 256
#define HCOLS 128
#define NTHREADS 1024

// smem layout (bytes)
#define OFF_WA   0
#define SZ_WA    (8 * NTHREADS * 16)       // 131072: fp16 w+alpha interleaved uint4 rows
#define OFF_YB   (OFF_WA + SZ_WA)
#define YSLOT_H  320                        // halves per slot: 8 chunks of (32 data + 8 pad)
#define SZ_YB    (2 * 4 * YSLOT_H * 2)      // 5120
#define OFF_Y0H  (OFF_YB + SZ_YB)
#define SZ_Y0H   (2 * 4 * HCOLS * 2)        // 2048
#define OFF_XT   (OFF_Y0H + SZ_Y0H)
#define SZ_XT    (2 * Tt * 4)               // 1024
#define OFF_RED  (OFF_XT + SZ_XT)
#define SZ_RED   (32 * 4)                   // redbuf[2 parities][16]
#define OFF_MB   (OFF_RED + SZ_RED)
#define SZ_MB    (4 * 8)                    // 4 slot barriers
#define SMEM_TOTAL (OFF_MB + SZ_MB)

__device__ __forceinline__ uint32_t my_cluster_rank() {
    uint32_t r; asm("mov.u32 %0, %%cluster_ctarank;" : "=r"(r)); return r;
}
__device__ __forceinline__ void cluster_sync_() {
    asm volatile("barrier.cluster.arrive.aligned;" ::: "memory");
    asm volatile("barrier.cluster.wait.aligned;" ::: "memory");
}
__device__ __forceinline__ uint32_t mapa_u32(uint32_t laddr, uint32_t rank) {
    uint32_t r;
    asm("mapa.shared::cluster.u32 %0, %1, %2;" : "=r"(r) : "r"(laddr), "r"(rank));
    return r;
}
__device__ __forceinline__ void st_remote_v4(uint32_t addr, uint4 v) {
    asm volatile("st.shared::cluster.v4.b32 [%0], {%1, %2, %3, %4};"
                 :: "r"(addr), "r"(v.x), "r"(v.y), "r"(v.z), "r"(v.w) : "memory");
}
__device__ __forceinline__ void mb_init(uint32_t addr, uint32_t count) {
    asm volatile("mbarrier.init.shared.b64 [%0], %1;" :: "r"(addr), "r"(count) : "memory");
}
__device__ __forceinline__ void mb_arrive_remote(uint32_t raddr) {
    asm volatile("mbarrier.arrive.release.cluster.shared::cluster.b64 _, [%0];"
                 :: "r"(raddr) : "memory");
}
__device__ __forceinline__ void mb_wait(uint32_t addr, uint32_t parity) {
    uint32_t done;
    asm volatile(
        "{\n\t.reg .pred p;\n\t"
        "mbarrier.try_wait.parity.acquire.cluster.shared::cta.b64 p, [%1], %2;\n\t"
        "selp.b32 %0, 1, 0, p;\n\t}"
        : "=r"(done) : "r"(addr), "r"(parity) : "memory");
    while (!done) {
        asm volatile(
            "{\n\t.reg .pred p;\n\t"
            "mbarrier.try_wait.parity.acquire.cluster.shared::cta.b64 p, [%1], %2, 0x989680;\n\t"
            "selp.b32 %0, 1, 0, p;\n\t}"
            : "=r"(done) : "r"(addr), "r"(parity) : "memory");
    }
}
__device__ __forceinline__ float tanh_ap(float x) {
    float y; asm("tanh.approx.f32 %0, %1;" : "=f"(y) : "f"(x)); return y;
}
__device__ __forceinline__ float grp8_sum(float v) {
    v += __shfl_xor_sync(0xffffffffu, v, 1);
    v += __shfl_xor_sync(0xffffffffu, v, 2);
    v += __shfl_xor_sync(0xffffffffu, v, 4);
    return v;
}

__global__ void __launch_bounds__(NTHREADS, 1) __cluster_dims__(4, 1, 1)
plastic_kernel(const int* __restrict__ x, const float* __restrict__ emb,
               const float* __restrict__ ws, const float* __restrict__ alphas,
               const float* __restrict__ etas, float* __restrict__ out)
{
    extern __shared__ __align__(16) char smem_raw[];
    uint4*  wa     = reinterpret_cast<uint4*>(smem_raw + OFF_WA);    // [8][1024]
    __half* ybuf   = reinterpret_cast<__half*>(smem_raw + OFF_YB);   // [2][4][320]
    __half* y0h    = reinterpret_cast<__half*>(smem_raw + OFF_Y0H);  // [2][4][128]
    int*    xtok   = reinterpret_cast<int*>(smem_raw + OFF_XT);      // [2][128]
    float*  redbuf = reinterpret_cast<float*>(smem_raw + OFF_RED);   // [2][16]
    const uint32_t sbase = (uint32_t)__cvta_generic_to_shared(smem_raw);

    const int tid     = threadIdx.x;
    const int cluster = blockIdx.x >> 2;
    const int rank    = (int)my_cluster_rank();
    const int layer   = rank >> 1;
    const int half_   = rank & 1;
    const int col_off = half_ * HCOLS;
    const int partner = rank ^ 1;
    const int col     = tid >> 3;            // 0..127
    const int colg    = col_off + col;
    const int dgrp    = tid & 7;             // 0..7, d-range [dgrp*32, dgrp*32+32)
    const int wid     = tid >> 5, lane = tid & 31;
    // y slot layout: 8 chunks of 40 halves (32 data + 8 pad) -> conflict-free dgrp reads
    const int pcol    = (colg >> 5) * 40 + (colg & 31);   // write pos for y[colg]
    const int ptid    = (tid >> 5) * 40 + (tid & 31);     // softmax read pos (tid<256)

#define MB_ADDR(s)     (sbase + OFF_MB + (uint32_t)((s) * 8))
#define YB_SLOT(b, s)  (ybuf + ((b) * 4 + (s)) * YSLOT_H)
#define Y0H_SLOT(b, s) (y0h + ((b) * 4 + (s)) * HCOLS)

    // ---- init shared ----
    for (int i = tid; i < 2 * 4 * YSLOT_H; i += NTHREADS) ybuf[i] = __ushort_as_half(0);
    for (int i = tid; i < 2 * 4 * HCOLS; i += NTHREADS) y0h[i] = __ushort_as_half(0);
    for (int i = tid; i < 2 * Tt; i += NTHREADS)
        xtok[i] = x[(cluster * 2 + (i >> 7)) * Tt + (i & 127)];
    if (tid == 0)
        for (int k = 0; k < 4; k++) mb_init(MB_ADDR(k), 2);
    __syncthreads();

    const float eta = etas[layer];
    const __half2 om2 = __float2half2_rn(1.0f - eta);

    __half2 h2a[16], h2b[16];
#pragma unroll
    for (int i = 0; i < 16; i++) { h2a[i] = __float2half2_rn(0.f); h2b[i] = h2a[i]; }

    // ---- stage w + alpha (fp16): thread o = c*8 + (d>>5) owns (32 d, 1 col) ----
    {
        const float* wsrc = ws     + (size_t)layer * Dd * Dd;
        const float* asrc = alphas + (size_t)layer * Dd * Dd;
        for (int idx = tid; idx < Dd * HCOLS; idx += NTHREADS) {
            int d = idx >> 7, c = idx & 127;
            int o = c * 8 + (d >> 5);
            int j = (d & 31) >> 3;
            int k = d & 7;
            reinterpret_cast<__half*>(&wa[(2 * j) * NTHREADS + o])[k] =
                __float2half(wsrc[(size_t)d * Dd + col_off + c]);
            reinterpret_cast<__half*>(&wa[(2 * j + 1) * NTHREADS + o])[k] =
                __float2half(asrc[(size_t)d * Dd + col_off + c]);
        }
    }
    __syncthreads();

    const uint32_t del_partner = mapa_u32(sbase, (uint32_t)partner) - sbase;
    const uint32_t del_inter   = (layer == 0)
        ? (mapa_u32(sbase, (uint32_t)(rank + 2)) - sbase)
        : (mapa_u32(sbase, (uint32_t)(rank - 2)) - sbase);

    cluster_sync_();   // barriers armed + buffers zeroed everywhere

    // ---- startup arrives (count=2 per slot-phase) ----
    if (tid == 0)
        mb_arrive_remote(MB_ADDR(0) + del_partner);
    if (tid == 32 && layer == 1) {   // credits to my L0 for slots 0..3
#pragma unroll
        for (int s = 0; s < 4; s++)
            mb_arrive_remote(MB_ADDR(s) + del_inter);
    }

    float* const outB0 = out + (size_t)(cluster * 2 + 0) * Tt * Dd;
    float* const outB1 = out + (size_t)(cluster * 2 + 1) * Tt * Dd;
    const uint4* wthr = wa + tid;

    float embreg0 = 0.f, embreg1 = 0.f;
    if (layer == 0) {
        embreg0 = __ldg(&emb[(size_t)xtok[0] * Dd + colg]);
        embreg1 = __ldg(&emb[(size_t)xtok[Tt] * Dd + colg]);
    }

    for (int t = 0; t < Tt; ++t) {
        const int sc = t & 3, sp = (t + 3) & 3, n3 = (t + 1) & 3;
        const uint32_t par = (uint32_t)((t >> 2) & 1);

        mb_wait(MB_ADDR(sc), par);   // one wait: partner(t-1) + inter(y0 data / credit)

        // ---- fused dual-batch dot: w/alpha loaded once ----
        const uint4* yp0 = reinterpret_cast<const uint4*>(YB_SLOT(0, sp)) + dgrp * 5;
        const uint4* yp1 = reinterpret_cast<const uint4*>(YB_SLOT(1, sp)) + dgrp * 5;
        __half2 accA0 = __float2half2_rn(0.f), accA1 = accA0;
        __half2 accB0 = accA0, accB1 = accA0;
#pragma unroll
        for (int j = 0; j < 4; j++) {
            uint4 wv = wthr[(2 * j) * NTHREADS];
            uint4 av = wthr[(2 * j + 1) * NTHREADS];
            uint4 y0v = yp0[j];
            uint4 y1v = yp1[j];
#define LANE(F)  F(x, 4 * j + 0, accA0, accB0)  F(y, 4 * j + 1, accA1, accB1) \
                 F(z, 4 * j + 2, accA0, accB0)  F(w, 4 * j + 3, accA1, accB1)
#define DOT2(c, hi, aA, aB)                                                        \
            {                                                                      \
                __half2 wl = *reinterpret_cast<__half2*>(&wv.c);                   \
                __half2 al = *reinterpret_cast<__half2*>(&av.c);                   \
                aA = __hfma2(*reinterpret_cast<__half2*>(&y0v.c),                  \
                             __hfma2(al, h2a[hi], wl), aA);                        \
                aB = __hfma2(*reinterpret_cast<__half2*>(&y1v.c),                  \
                             __hfma2(al, h2b[hi], wl), aB);                        \
            }
            LANE(DOT2)
#undef DOT2
#undef LANE
        }
        float2 fA = __half22float2(__hadd2(accA0, accA1));
        float2 fB = __half22float2(__hadd2(accB0, accB1));
        float acc0 = grp8_sum(fA.x + fA.y);
        float acc1 = grp8_sum(fB.x + fB.y);

        float inp0 = (layer == 0) ? embreg0 : __half2float(Y0H_SLOT(0, sc)[col]);
        float inp1 = (layer == 0) ? embreg1 : __half2float(Y0H_SLOT(1, sc)[col]);
        float y0 = tanh_ap(acc0 + inp0);
        float y1 = tanh_ap(acc1 + inp1);

        // ---- local y writes only (one thread per column) ----
        if (dgrp == 0) {
            YB_SLOT(0, sc)[pcol] = __float2half(y0);
            YB_SLOT(1, sc)[pcol] = __float2half(y1);
        }
        __syncthreads();   // local slab complete & visible

        // ---- vectorized exchange: warp 0 -> partner, warp 1 -> inter ----
        if (wid == 0) {
            const int B = lane >> 4, l = lane & 15;
            const int ch = half_ * 4 + (l >> 2), q = l & 3;
            const char* src = reinterpret_cast<const char*>(YB_SLOT(B, sc))
                              + ch * 80 + q * 16;
            uint4 v = *reinterpret_cast<const uint4*>(src);
            st_remote_v4((uint32_t)__cvta_generic_to_shared(src) + del_partner, v);
            __syncwarp();
            if (lane == 0) mb_arrive_remote(MB_ADDR(n3) + del_partner);
        } else if (wid == 1) {
            if (layer == 0) {
                const int B = lane >> 4, l = lane & 15;
                const int ch = half_ * 4 + (l >> 2), q = l & 3;
                const char* src = reinterpret_cast<const char*>(YB_SLOT(B, sc))
                                  + ch * 80 + q * 16;
                uint4 v = *reinterpret_cast<const uint4*>(src);
                char* dst = reinterpret_cast<char*>(Y0H_SLOT(B, sc)) + l * 16;
                st_remote_v4((uint32_t)__cvta_generic_to_shared(dst) + del_inter, v);
                __syncwarp();
            }
            if (lane == 0) mb_arrive_remote(MB_ADDR(sc) + del_inter);
        }

        // ---- deferred: hebb (re-reads old y), emb prefetch, softmax ----
        {
            __half2 ey0 = __float2half2_rn(eta * y0);
            __half2 ey1 = __float2half2_rn(eta * y1);
#pragma unroll
            for (int j = 0; j < 4; j++) {
                uint4 y0v = yp0[j];
                uint4 y1v = yp1[j];
#define HEB(c, hi)                                                                 \
                h2a[hi] = __hfma2(h2a[hi], om2,                                    \
                    __hmul2(*reinterpret_cast<__half2*>(&y0v.c), ey0));            \
                h2b[hi] = __hfma2(h2b[hi], om2,                                    \
                    __hmul2(*reinterpret_cast<__half2*>(&y1v.c), ey1));
                HEB(x, 4 * j + 0) HEB(y, 4 * j + 1) HEB(z, 4 * j + 2) HEB(w, 4 * j + 3)
#undef HEB
            }
        }
        if (layer == 0 && t + 1 < Tt) {
            embreg0 = __ldg(&emb[(size_t)xtok[t + 1] * Dd + colg]);
            embreg1 = __ldg(&emb[(size_t)xtok[Tt + t + 1] * Dd + colg]);
        }

        if (layer == 1 && t >= 1) {
            float* rb = redbuf + (t & 1) * 16;
            float ex0 = 0.f, ex1 = 0.f;
            if (tid < Dd) {
                float v0 = __half2float(YB_SLOT(0, sp)[ptid]);
                float v1 = __half2float(YB_SLOT(1, sp)[ptid]);
                ex0 = __expf(__fdividef(1.0f, 1.0f + __expf(-v0)));
                ex1 = __expf(__fdividef(1.0f, 1.0f + __expf(-v1)));
            }
            float w0 = ex0, w1 = ex1;
#pragma unroll
            for (int o = 16; o >= 1; o >>= 1) {
                w0 += __shfl_xor_sync(0xffffffffu, w0, o);
                w1 += __shfl_xor_sync(0xffffffffu, w1, o);
            }
            if (wid < 8 && lane == 0) { rb[wid] = w0; rb[8 + wid] = w1; }
            __syncthreads();
            float t0 = 0.f, t1 = 0.f;
#pragma unroll
            for (int k = 0; k < 8; k++) { t0 += rb[k]; t1 += rb[8 + k]; }
            if (tid >= col_off && tid < col_off + HCOLS) {
                outB0[(size_t)(t - 1) * Dd + tid] = __fdividef(ex0, t0);
                outB1[(size_t)(t - 1) * Dd + tid] = __fdividef(ex1, t1);
            }
        }
    }

    // ---- epilogue ----
    if (layer == 0) {
        if (tid == 32)   // bonus inter so L1's final slot-0 phase completes
            mb_arrive_remote(MB_ADDR(0) + del_inter);
    } else {
        mb_wait(MB_ADDR(0), 0u);
        const int sp = 3;   // slot of y1(127)
        float* rb = redbuf;  // parity-0 half; last loop softmax used parity 1
        float ex0 = 0.f, ex1 = 0.f;
        if (tid < Dd) {
            float v0 = __half2float(YB_SLOT(0, sp)[ptid]);
            float v1 = __half2float(YB_SLOT(1, sp)[ptid]);
            ex0 = __expf(__fdividef(1.0f, 1.0f + __expf(-v0)));
            ex1 = __expf(__fdividef(1.0f, 1.0f + __expf(-v1)));
        }
        float w0 = ex0, w1 = ex1;
#pragma unroll
        for (int o = 16; o >= 1; o >>= 1) {
            w0 += __shfl_xor_sync(0xffffffffu, w0, o);
            w1 += __shfl_xor_sync(0xffffffffu, w1, o);
        }
        if (wid < 8 && lane == 0) { rb[wid] = w0; rb[8 + wid] = w1; }
        __syncthreads();
        float t0 = 0.f, t1 = 0.f;
#pragma unroll
        for (int k = 0; k < 8; k++) { t0 += rb[k]; t1 += rb[8 + k]; }
        if (tid >= col_off && tid < col_off + HCOLS) {
            outB0[(size_t)(Tt - 1) * Dd + tid] = __fdividef(ex0, t0);
            outB1[(size_t)(Tt - 1) * Dd + tid] = __fdividef(ex1, t1);
        }
    }

    cluster_sync_();
}

extern "C" void kernel_launch(void* const* d_in, const int* in_sizes, int n_in,
                              void* d_out, int out_size) {
    const int*   x      = (const int*)d_in[0];
    const float* emb    = (const float*)d_in[1];
    const float* ws     = (const float*)d_in[2];
    const float* alphas = (const float*)d_in[3];
    const float* etas   = (const float*)d_in[4];
    cudaFuncSetAttribute(plastic_kernel,
                         cudaFuncAttributeMaxDynamicSharedMemorySize, SMEM_TOTAL);
    plastic_kernel<<<(Bb / 2) * 4, NTHREADS, SMEM_TOTAL>>>(
        x, emb, ws, alphas, etas, (float*)d_out);
}